// round 2
// baseline (speedup 1.0000x reference)
#include <cuda_runtime.h>
#include <math.h>

// Problem constants
#define B    512
#define T    365
#define INP  10
#define H    256
#define OUT  20

// Decomposition: 4 batch groups x 32 column groups = 128 persistent CTAs
#define GB        4
#define GC        32
#define NCTA      (GB * GC)
#define NTHREADS  512
#define MB        128   // batch rows per CTA
#define HC        8     // h-columns per CTA (gate rows = 3*HC = 24)
#define WS        260   // padded smem row stride (floats) -> conflict-free LDS.128

// Persistent state (double buffered), scratch via __device__ globals (no allocs).
__device__ float g_h0[2][B * H];
__device__ float g_h1[2][B * H];
__device__ unsigned g_count = 0;
__device__ unsigned g_gen = 0;

__device__ __forceinline__ void grid_sync() {
    __threadfence();          // make this thread's L2 writes visible
    __syncthreads();          // all CTA threads' writes precede thread0's arrival
    if (threadIdx.x == 0) {
        unsigned gen = *(volatile unsigned*)&g_gen;
        if (atomicAdd(&g_count, 1u) == NCTA - 1u) {
            g_count = 0u;
            __threadfence();
            atomicAdd(&g_gen, 1u);
        } else {
            while (*(volatile unsigned*)&g_gen == gen) { }
        }
    }
    __syncthreads();
}

// Packed dual-FMA (Blackwell f32x2). ptxas never emits this from C++;
// explicit PTX is required. Lanes: lo/hi of the 64-bit regs independently.
__device__ __forceinline__ void ffma2(unsigned long long& d,
                                      unsigned long long a,
                                      unsigned long long b) {
    asm("fma.rn.f32x2 %0, %1, %2, %0;" : "+l"(d) : "l"(a), "l"(b));
}

// Sum the two packed partial sums.
__device__ __forceinline__ float accsum(unsigned long long a) {
    return __uint_as_float((unsigned)a) + __uint_as_float((unsigned)(a >> 32));
}

// Accumulate 3 gate dot-products over K=256 for 2 batch rows, packed k-pairs.
// hin: global fp32 [B][H] via L2 (__ldcg). sW: smem, rows (g*8+jc), stride WS.
// acc[g*2+r] holds (sum over even k, sum over odd k) packed in 64 bits.
__device__ __forceinline__ void gemm3(const float* __restrict__ hin, int b0,
                                      const float* __restrict__ sW, int jc,
                                      unsigned long long* __restrict__ acc /*[6]*/) {
    const ulonglong2* __restrict__ hp  = reinterpret_cast<const ulonglong2*>(hin);
    const ulonglong2* __restrict__ w0p = reinterpret_cast<const ulonglong2*>(sW + (0 + jc) * WS);
    const ulonglong2* __restrict__ w1p = reinterpret_cast<const ulonglong2*>(sW + (8 + jc) * WS);
    const ulonglong2* __restrict__ w2p = reinterpret_cast<const ulonglong2*>(sW + (16 + jc) * WS);
    const ulonglong2* __restrict__ h0p = hp + (size_t)(b0 + 0) * (H / 4);
    const ulonglong2* __restrict__ h1p = hp + (size_t)(b0 + 1) * (H / 4);
#pragma unroll 4
    for (int k4 = 0; k4 < H / 4; ++k4) {
        ulonglong2 hv0 = __ldcg(h0p + k4);
        ulonglong2 hv1 = __ldcg(h1p + k4);
        ulonglong2 w0 = w0p[k4];
        ulonglong2 w1 = w1p[k4];
        ulonglong2 w2 = w2p[k4];
        ffma2(acc[0], hv0.x, w0.x); ffma2(acc[0], hv0.y, w0.y);
        ffma2(acc[1], hv1.x, w0.x); ffma2(acc[1], hv1.y, w0.y);
        ffma2(acc[2], hv0.x, w1.x); ffma2(acc[2], hv0.y, w1.y);
        ffma2(acc[3], hv1.x, w1.x); ffma2(acc[3], hv1.y, w1.y);
        ffma2(acc[4], hv0.x, w2.x); ffma2(acc[4], hv0.y, w2.y);
        ffma2(acc[5], hv1.x, w2.x); ffma2(acc[5], hv1.y, w2.y);
    }
}

__device__ __forceinline__ float sigmoidf_(float v) {
    return 1.0f / (1.0f + expf(-v));
}

__global__ void __launch_bounds__(NTHREADS, 1)
gru_persistent_kernel(const float* __restrict__ x,
                      const float* __restrict__ W_ih0, const float* __restrict__ W_hh0,
                      const float* __restrict__ b_ih0, const float* __restrict__ b_hh0,
                      const float* __restrict__ W_ih1, const float* __restrict__ W_hh1,
                      const float* __restrict__ b_ih1, const float* __restrict__ b_hh1,
                      const float* __restrict__ W_out, const float* __restrict__ b_out,
                      float* __restrict__ out) {
    extern __shared__ float sm[];
    float* sWh0 = sm;                       // 24*WS
    float* sWi1 = sWh0 + 24 * WS;           // 24*WS
    float* sWh1 = sWi1 + 24 * WS;           // 24*WS
    float* sWi0 = sWh1 + 24 * WS;           // 24*12 (padded)
    float* sBi0 = sWi0 + 24 * 12;           // 24
    float* sBh0 = sBi0 + 24;                // 24
    float* sBi1 = sBh0 + 24;                // 24
    float* sBh1 = sBi1 + 24;                // 24

    const int tid = threadIdx.x;
    const int gb  = blockIdx.x >> 5;        // batch group 0..3
    const int gc  = blockIdx.x & 31;        // column group 0..31
    const int c0  = gc * HC;
    const int jc  = tid & 7;                // h-column within CTA
    const int rg  = tid >> 3;               // row group 0..63
    const int b0  = gb * MB + rg * 2;       // first of 2 batch rows
    const int c   = c0 + jc;                // global h column

    // ---- Prologue: weights -> smem (once; resident all 365 steps) ----
    for (int idx = tid; idx < 24 * 256; idx += NTHREADS) {
        int row = idx >> 8, k = idx & 255;
        int g = row >> 3, j = row & 7;
        int grow = g * H + c0 + j;
        sWh0[row * WS + k] = W_hh0[grow * H + k];
        sWi1[row * WS + k] = W_ih1[grow * H + k];
        sWh1[row * WS + k] = W_hh1[grow * H + k];
    }
    for (int idx = tid; idx < 24 * INP; idx += NTHREADS) {
        int row = idx / INP, i = idx - row * INP;
        int g = row >> 3, j = row & 7;
        int grow = g * H + c0 + j;
        sWi0[row * 12 + i] = W_ih0[grow * INP + i];
    }
    if (tid < 24) {
        int g = tid >> 3, j = tid & 7;
        int grow = g * H + c0 + j;
        sBi0[tid] = b_ih0[grow];
        sBh0[tid] = b_hh0[grow];
        sBi1[tid] = b_ih1[grow];
        sBh1[tid] = b_hh1[grow];
    }

    // Zero initial hidden state (buffers read at t=0). Every launch (determinism).
    for (int idx = blockIdx.x * NTHREADS + tid; idx < B * H; idx += NCTA * NTHREADS) {
        __stcg(&g_h0[0][idx], 0.0f);
        __stcg(&g_h1[0][idx], 0.0f);
    }
    __syncthreads();
    grid_sync();

    // ---- Main sequential loop ----
    for (int t = 0; t < T; ++t) {
        const float* h0r = g_h0[t & 1];
        float*       h0w = g_h0[(t & 1) ^ 1];
        const float* h1r = g_h1[t & 1];
        float*       h1w = g_h1[(t & 1) ^ 1];

        // ===== Layer 0: x_t @ W_ih0^T (scalar, K=10)  +  h0 @ W_hh0^T (packed) =====
        float ai[6];
#pragma unroll
        for (int g = 0; g < 3; ++g)
#pragma unroll
            for (int r = 0; r < 2; ++r)
                ai[g * 2 + r] = sBi0[g * 8 + jc];

#pragma unroll
        for (int r = 0; r < 2; ++r) {
            const float* xr = x + ((size_t)(b0 + r) * T + t) * INP;
#pragma unroll
            for (int i = 0; i < INP; ++i) {
                float xv = __ldg(&xr[i]);
#pragma unroll
                for (int g = 0; g < 3; ++g)
                    ai[g * 2 + r] += xv * sWi0[(g * 8 + jc) * 12 + i];
            }
        }

        unsigned long long ah[6];
#pragma unroll
        for (int q = 0; q < 6; ++q) ah[q] = 0ull;
        gemm3(h0r, b0, sWh0, jc, ah);

#pragma unroll
        for (int r = 0; r < 2; ++r) {
            float gr = accsum(ah[0 * 2 + r]) + sBh0[0 * 8 + jc];
            float gz = accsum(ah[1 * 2 + r]) + sBh0[1 * 8 + jc];
            float gn = accsum(ah[2 * 2 + r]) + sBh0[2 * 8 + jc];
            float rr = sigmoidf_(ai[0 * 2 + r] + gr);
            float zz = sigmoidf_(ai[1 * 2 + r] + gz);
            float nn = tanhf(ai[2 * 2 + r] + rr * gn);
            float hold = __ldcg(&h0r[(size_t)(b0 + r) * H + c]);
            __stcg(&h0w[(size_t)(b0 + r) * H + c], (1.0f - zz) * nn + zz * hold);
        }

        grid_sync();   // h0_t complete, visible in L2

        // ===== Layer 1: h0_t @ W_ih1^T  +  h1 @ W_hh1^T (both packed) =====
        unsigned long long aiq[6], ahq[6];
#pragma unroll
        for (int q = 0; q < 6; ++q) { aiq[q] = 0ull; ahq[q] = 0ull; }
        gemm3(h0w, b0, sWi1, jc, aiq);
        gemm3(h1r, b0, sWh1, jc, ahq);

#pragma unroll
        for (int r = 0; r < 2; ++r) {
            float ir = accsum(aiq[0 * 2 + r]) + sBi1[0 * 8 + jc];
            float iz = accsum(aiq[1 * 2 + r]) + sBi1[1 * 8 + jc];
            float in = accsum(aiq[2 * 2 + r]) + sBi1[2 * 8 + jc];
            float hr = accsum(ahq[0 * 2 + r]) + sBh1[0 * 8 + jc];
            float hz = accsum(ahq[1 * 2 + r]) + sBh1[1 * 8 + jc];
            float hn = accsum(ahq[2 * 2 + r]) + sBh1[2 * 8 + jc];
            float rr = sigmoidf_(ir + hr);
            float zz = sigmoidf_(iz + hz);
            float nn = tanhf(in + rr * hn);
            float hold = __ldcg(&h1r[(size_t)(b0 + r) * H + c]);
            __stcg(&h1w[(size_t)(b0 + r) * H + c], (1.0f - zz) * nn + zz * hold);
        }

        grid_sync();   // h1_t complete
    }

    // ---- Epilogue: logits + softmax, one warp per batch row ----
    const float* hfin = g_h1[T & 1];   // final h1 buffer
    int gw = blockIdx.x * (NTHREADS / 32) + (tid >> 5);
    int lane = tid & 31;
    if (gw < B) {
        const float* hrow = hfin + (size_t)gw * H;
        float hk[8];
#pragma unroll
        for (int j2 = 0; j2 < 8; ++j2) hk[j2] = __ldcg(&hrow[lane + 32 * j2]);

        float logits[OUT];
#pragma unroll
        for (int o = 0; o < OUT; ++o) {
            float p = 0.0f;
#pragma unroll
            for (int j2 = 0; j2 < 8; ++j2)
                p += hk[j2] * __ldg(&W_out[o * H + lane + 32 * j2]);
#pragma unroll
            for (int s = 16; s > 0; s >>= 1)
                p += __shfl_xor_sync(0xffffffffu, p, s);
            logits[o] = p + __ldg(&b_out[o]);
        }
        float mx = logits[0];
#pragma unroll
        for (int o = 1; o < OUT; ++o) mx = fmaxf(mx, logits[o]);
        float sum = 0.0f;
#pragma unroll
        for (int o = 0; o < OUT; ++o) { logits[o] = expf(logits[o] - mx); sum += logits[o]; }
        float inv = 1.0f / sum;
        if (lane == 0) {
#pragma unroll
            for (int o = 0; o < OUT; ++o)
                out[(size_t)gw * OUT + o] = logits[o] * inv;
        }
    }
}

extern "C" void kernel_launch(void* const* d_in, const int* in_sizes, int n_in,
                              void* d_out, int out_size) {
    const float* x      = (const float*)d_in[0];
    // d_in[1] = times (unused), d_in[2] = interpolation_method (unused)
    const float* W_ih0  = (const float*)d_in[3];
    const float* W_hh0  = (const float*)d_in[4];
    const float* b_ih0  = (const float*)d_in[5];
    const float* b_hh0  = (const float*)d_in[6];
    const float* W_ih1  = (const float*)d_in[7];
    const float* W_hh1  = (const float*)d_in[8];
    const float* b_ih1  = (const float*)d_in[9];
    const float* b_hh1  = (const float*)d_in[10];
    const float* W_out  = (const float*)d_in[11];
    const float* b_out  = (const float*)d_in[12];
    float* out = (float*)d_out;

    const size_t smem_bytes = (size_t)(3 * 24 * WS + 24 * 12 + 4 * 24) * sizeof(float); // 76,416 B
    cudaFuncSetAttribute(gru_persistent_kernel,
                         cudaFuncAttributeMaxDynamicSharedMemorySize, (int)smem_bytes);

    gru_persistent_kernel<<<NCTA, NTHREADS, smem_bytes>>>(
        x, W_ih0, W_hh0, b_ih0, b_hh0,
        W_ih1, W_hh1, b_ih1, b_hh1,
        W_out, b_out, out);
}

// round 3
// speedup vs baseline: 1.3157x; 1.3157x over previous
#include <cuda_runtime.h>
#include <math.h>

// Problem constants
#define B    512
#define T    365
#define INP  10
#define H    256
#define OUT  20

// Decomposition: 4 batch groups x 32 column groups = 128 persistent CTAs
#define GB        4
#define GC        32
#define NCTA      (GB * GC)
#define NTHREADS  256
#define MB        128   // batch rows per CTA
#define HC        8     // h-columns per CTA (gate rows = 3*HC = 24)
#define WS        260   // padded smem weight row stride (floats)
#define KC        64    // k-chunk staged per round
#define NCH       (H / KC)   // 4 chunks
#define SS        68    // staged h row stride (floats): 16B-aligned, conflict-free

// Persistent state (double buffered), scratch via __device__ globals (no allocs).
__device__ float g_h0[2][B * H];
__device__ float g_h1[2][B * H];
__device__ unsigned g_count = 0;
__device__ unsigned g_gen = 0;

__device__ __forceinline__ void grid_sync() {
    __threadfence();
    __syncthreads();
    if (threadIdx.x == 0) {
        unsigned gen = *(volatile unsigned*)&g_gen;
        if (atomicAdd(&g_count, 1u) == NCTA - 1u) {
            g_count = 0u;
            __threadfence();
            atomicAdd(&g_gen, 1u);
        } else {
            while (*(volatile unsigned*)&g_gen == gen) { }
        }
    }
    __syncthreads();
}

// Packed dual-FMA (Blackwell f32x2); ptxas never auto-fuses, explicit PTX.
__device__ __forceinline__ void ffma2(unsigned long long& d,
                                      unsigned long long a,
                                      unsigned long long b) {
    asm("fma.rn.f32x2 %0, %1, %2, %0;" : "+l"(d) : "l"(a), "l"(b));
}
__device__ __forceinline__ float accsum(unsigned long long a) {
    return __uint_as_float((unsigned)a) + __uint_as_float((unsigned)(a >> 32));
}

// Stage hbase[MB][H] (global, L2) into smem chunks and accumulate the 3 gate
// dot products for 4 batch rows (local rows rg, rg+32, rg+64, rg+96).
// acc[g*4+i] packed k-pairs. Register double buffer hides staging latency.
__device__ __forceinline__ void stage_and_gemm3(
    const float* __restrict__ hbase,   // global, CTA's batch slice
    float* __restrict__ sbuf,          // smem [MB][SS]
    const float* __restrict__ sW,      // smem weights, 24 x WS
    int tid, int jc, int rg,
    unsigned long long* __restrict__ acc /*[12]*/) {
    const int row_s = tid >> 4;    // 0..15
    const int col4  = tid & 15;    // 0..15 (float4 column within chunk)

    float4 regs[8];
#pragma unroll
    for (int i = 0; i < 8; ++i) {
        int row = i * 16 + row_s;
        regs[i] = __ldcg(reinterpret_cast<const float4*>(hbase + (size_t)row * H) + col4);
    }

    for (int cc = 0; cc < NCH; ++cc) {
        __syncthreads();   // previous chunk fully consumed
#pragma unroll
        for (int i = 0; i < 8; ++i) {
            int row = i * 16 + row_s;
            *reinterpret_cast<float4*>(sbuf + row * SS + col4 * 4) = regs[i];
        }
        __syncthreads();   // chunk visible
        if (cc + 1 < NCH) {
#pragma unroll
            for (int i = 0; i < 8; ++i) {
                int row = i * 16 + row_s;
                regs[i] = __ldcg(reinterpret_cast<const float4*>(
                              hbase + (size_t)row * H + (cc + 1) * KC) + col4);
            }
        }
        const ulonglong2* __restrict__ w0p =
            reinterpret_cast<const ulonglong2*>(sW + (0 * 8 + jc) * WS + cc * KC);
        const ulonglong2* __restrict__ w1p =
            reinterpret_cast<const ulonglong2*>(sW + (1 * 8 + jc) * WS + cc * KC);
        const ulonglong2* __restrict__ w2p =
            reinterpret_cast<const ulonglong2*>(sW + (2 * 8 + jc) * WS + cc * KC);
        const ulonglong2* __restrict__ h0p =
            reinterpret_cast<const ulonglong2*>(sbuf + (rg + 0)  * SS);
        const ulonglong2* __restrict__ h1p =
            reinterpret_cast<const ulonglong2*>(sbuf + (rg + 32) * SS);
        const ulonglong2* __restrict__ h2p =
            reinterpret_cast<const ulonglong2*>(sbuf + (rg + 64) * SS);
        const ulonglong2* __restrict__ h3p =
            reinterpret_cast<const ulonglong2*>(sbuf + (rg + 96) * SS);
#pragma unroll 4
        for (int k4 = 0; k4 < KC / 4; ++k4) {
            ulonglong2 w0 = w0p[k4], w1 = w1p[k4], w2 = w2p[k4];
            ulonglong2 hv0 = h0p[k4], hv1 = h1p[k4], hv2 = h2p[k4], hv3 = h3p[k4];
            ffma2(acc[0],  hv0.x, w0.x); ffma2(acc[0],  hv0.y, w0.y);
            ffma2(acc[1],  hv1.x, w0.x); ffma2(acc[1],  hv1.y, w0.y);
            ffma2(acc[2],  hv2.x, w0.x); ffma2(acc[2],  hv2.y, w0.y);
            ffma2(acc[3],  hv3.x, w0.x); ffma2(acc[3],  hv3.y, w0.y);
            ffma2(acc[4],  hv0.x, w1.x); ffma2(acc[4],  hv0.y, w1.y);
            ffma2(acc[5],  hv1.x, w1.x); ffma2(acc[5],  hv1.y, w1.y);
            ffma2(acc[6],  hv2.x, w1.x); ffma2(acc[6],  hv2.y, w1.y);
            ffma2(acc[7],  hv3.x, w1.x); ffma2(acc[7],  hv3.y, w1.y);
            ffma2(acc[8],  hv0.x, w2.x); ffma2(acc[8],  hv0.y, w2.y);
            ffma2(acc[9],  hv1.x, w2.x); ffma2(acc[9],  hv1.y, w2.y);
            ffma2(acc[10], hv2.x, w2.x); ffma2(acc[10], hv2.y, w2.y);
            ffma2(acc[11], hv3.x, w2.x); ffma2(acc[11], hv3.y, w2.y);
        }
    }
}

__device__ __forceinline__ float sigmoidf_(float v) {
    return 1.0f / (1.0f + expf(-v));
}

__global__ void __launch_bounds__(NTHREADS, 1)
gru_persistent_kernel(const float* __restrict__ x,
                      const float* __restrict__ W_ih0, const float* __restrict__ W_hh0,
                      const float* __restrict__ b_ih0, const float* __restrict__ b_hh0,
                      const float* __restrict__ W_ih1, const float* __restrict__ W_hh1,
                      const float* __restrict__ b_ih1, const float* __restrict__ b_hh1,
                      const float* __restrict__ W_out, const float* __restrict__ b_out,
                      float* __restrict__ out) {
    extern __shared__ float sm[];
    float* sWh0 = sm;                       // 24*WS
    float* sWi1 = sWh0 + 24 * WS;           // 24*WS
    float* sWh1 = sWi1 + 24 * WS;           // 24*WS
    float* sWi0 = sWh1 + 24 * WS;           // 24*12
    float* sBi0 = sWi0 + 24 * 12;           // 24
    float* sBh0 = sBi0 + 24;
    float* sBi1 = sBh0 + 24;
    float* sBh1 = sBi1 + 24;
    float* sbuf = sBh1 + 24;                // MB*SS staged h chunk

    const int tid = threadIdx.x;
    const int gb  = blockIdx.x >> 5;        // batch group 0..3
    const int gc  = blockIdx.x & 31;        // column group 0..31
    const int c0  = gc * HC;
    const int jc  = tid & 7;                // h-column within CTA
    const int rg  = tid >> 3;               // 0..31; rows rg+32i (strided)
    const int c   = c0 + jc;                // global h column
    const int gb0 = gb * MB;                // CTA's first batch row

    // ---- Prologue: weights -> smem (once; resident all 365 steps) ----
    for (int idx = tid; idx < 24 * 256; idx += NTHREADS) {
        int row = idx >> 8, k = idx & 255;
        int g = row >> 3, j = row & 7;
        int grow = g * H + c0 + j;
        sWh0[row * WS + k] = W_hh0[grow * H + k];
        sWi1[row * WS + k] = W_ih1[grow * H + k];
        sWh1[row * WS + k] = W_hh1[grow * H + k];
    }
    for (int idx = tid; idx < 24 * INP; idx += NTHREADS) {
        int row = idx / INP, i = idx - row * INP;
        int g = row >> 3, j = row & 7;
        int grow = g * H + c0 + j;
        sWi0[row * 12 + i] = W_ih0[grow * INP + i];
    }
    if (tid < 24) {
        int g = tid >> 3, j = tid & 7;
        int grow = g * H + c0 + j;
        sBi0[tid] = b_ih0[grow];
        sBh0[tid] = b_hh0[grow];
        sBi1[tid] = b_ih1[grow];
        sBh1[tid] = b_hh1[grow];
    }

    // Zero initial hidden state (read at t=0). Every launch (determinism).
    for (int idx = blockIdx.x * NTHREADS + tid; idx < B * H; idx += NCTA * NTHREADS) {
        __stcg(&g_h0[0][idx], 0.0f);
        __stcg(&g_h1[0][idx], 0.0f);
    }
    __syncthreads();
    grid_sync();

    // ---- Main sequential loop ----
    for (int t = 0; t < T; ++t) {
        const float* h0r = g_h0[t & 1];
        float*       h0w = g_h0[(t & 1) ^ 1];
        const float* h1r = g_h1[t & 1];
        float*       h1w = g_h1[(t & 1) ^ 1];

        // ===== Layer 0: x_t @ W_ih0^T (scalar K=10) + h0 @ W_hh0^T (staged) =====
        float ai[12];
#pragma unroll
        for (int g = 0; g < 3; ++g)
#pragma unroll
            for (int i = 0; i < 4; ++i)
                ai[g * 4 + i] = sBi0[g * 8 + jc];
#pragma unroll
        for (int i = 0; i < 4; ++i) {
            const float* xr = x + ((size_t)(gb0 + rg + 32 * i) * T + t) * INP;
#pragma unroll
            for (int k = 0; k < INP; ++k) {
                float xv = __ldg(&xr[k]);
#pragma unroll
                for (int g = 0; g < 3; ++g)
                    ai[g * 4 + i] += xv * sWi0[(g * 8 + jc) * 12 + k];
            }
        }

        unsigned long long ah[12];
#pragma unroll
        for (int q = 0; q < 12; ++q) ah[q] = 0ull;
        stage_and_gemm3(h0r + (size_t)gb0 * H, sbuf, sWh0, tid, jc, rg, ah);

#pragma unroll
        for (int i = 0; i < 4; ++i) {
            int brow = gb0 + rg + 32 * i;
            float gr = accsum(ah[0 * 4 + i]) + sBh0[0 * 8 + jc];
            float gz = accsum(ah[1 * 4 + i]) + sBh0[1 * 8 + jc];
            float gn = accsum(ah[2 * 4 + i]) + sBh0[2 * 8 + jc];
            float rr = sigmoidf_(ai[0 * 4 + i] + gr);
            float zz = sigmoidf_(ai[1 * 4 + i] + gz);
            float nn = tanhf(ai[2 * 4 + i] + rr * gn);
            float hold = __ldcg(&h0r[(size_t)brow * H + c]);
            __stcg(&h0w[(size_t)brow * H + c], (1.0f - zz) * nn + zz * hold);
        }

        // ===== Layer 1 part A (prev-step h1; independent of this step's h0) =====
        unsigned long long ahq[12];
#pragma unroll
        for (int q = 0; q < 12; ++q) ahq[q] = 0ull;
        stage_and_gemm3(h1r + (size_t)gb0 * H, sbuf, sWh1, tid, jc, rg, ahq);

        grid_sync();   // h0_t complete chip-wide

        // ===== Layer 1 part B: h0_t @ W_ih1^T =====
        unsigned long long aiq[12];
#pragma unroll
        for (int q = 0; q < 12; ++q) aiq[q] = 0ull;
        stage_and_gemm3(h0w + (size_t)gb0 * H, sbuf, sWi1, tid, jc, rg, aiq);

#pragma unroll
        for (int i = 0; i < 4; ++i) {
            int brow = gb0 + rg + 32 * i;
            float ir = accsum(aiq[0 * 4 + i]) + sBi1[0 * 8 + jc];
            float iz = accsum(aiq[1 * 4 + i]) + sBi1[1 * 8 + jc];
            float in = accsum(aiq[2 * 4 + i]) + sBi1[2 * 8 + jc];
            float hr = accsum(ahq[0 * 4 + i]) + sBh1[0 * 8 + jc];
            float hz = accsum(ahq[1 * 4 + i]) + sBh1[1 * 8 + jc];
            float hn = accsum(ahq[2 * 4 + i]) + sBh1[2 * 8 + jc];
            float rr = sigmoidf_(ir + hr);
            float zz = sigmoidf_(iz + hz);
            float nn = tanhf(in + rr * hn);
            float hold = __ldcg(&h1r[(size_t)brow * H + c]);
            __stcg(&h1w[(size_t)brow * H + c], (1.0f - zz) * nn + zz * hold);
        }

        grid_sync();   // h1_t complete
    }

    // ---- Epilogue: logits + softmax, one warp per batch row ----
    const float* hfin = g_h1[T & 1];
    int gw = blockIdx.x * (NTHREADS / 32) + (tid >> 5);
    int lane = tid & 31;
    if (gw < B) {
        const float* hrow = hfin + (size_t)gw * H;
        float hk[8];
#pragma unroll
        for (int j2 = 0; j2 < 8; ++j2) hk[j2] = __ldcg(&hrow[lane + 32 * j2]);

        float logits[OUT];
#pragma unroll
        for (int o = 0; o < OUT; ++o) {
            float p = 0.0f;
#pragma unroll
            for (int j2 = 0; j2 < 8; ++j2)
                p += hk[j2] * __ldg(&W_out[o * H + lane + 32 * j2]);
#pragma unroll
            for (int s = 16; s > 0; s >>= 1)
                p += __shfl_xor_sync(0xffffffffu, p, s);
            logits[o] = p + __ldg(&b_out[o]);
        }
        float mx = logits[0];
#pragma unroll
        for (int o = 1; o < OUT; ++o) mx = fmaxf(mx, logits[o]);
        float sum = 0.0f;
#pragma unroll
        for (int o = 0; o < OUT; ++o) { logits[o] = expf(logits[o] - mx); sum += logits[o]; }
        float inv = 1.0f / sum;
        if (lane == 0) {
#pragma unroll
            for (int o = 0; o < OUT; ++o)
                out[(size_t)gw * OUT + o] = logits[o] * inv;
        }
    }
}

extern "C" void kernel_launch(void* const* d_in, const int* in_sizes, int n_in,
                              void* d_out, int out_size) {
    const float* x      = (const float*)d_in[0];
    // d_in[1] = times (unused), d_in[2] = interpolation_method (unused)
    const float* W_ih0  = (const float*)d_in[3];
    const float* W_hh0  = (const float*)d_in[4];
    const float* b_ih0  = (const float*)d_in[5];
    const float* b_hh0  = (const float*)d_in[6];
    const float* W_ih1  = (const float*)d_in[7];
    const float* W_hh1  = (const float*)d_in[8];
    const float* b_ih1  = (const float*)d_in[9];
    const float* b_hh1  = (const float*)d_in[10];
    const float* W_out  = (const float*)d_in[11];
    const float* b_out  = (const float*)d_in[12];
    float* out = (float*)d_out;

    const size_t smem_bytes =
        (size_t)(3 * 24 * WS + 24 * 12 + 4 * 24 + MB * SS) * sizeof(float); // ~111 KB
    cudaFuncSetAttribute(gru_persistent_kernel,
                         cudaFuncAttributeMaxDynamicSharedMemorySize, (int)smem_bytes);

    gru_persistent_kernel<<<NCTA, NTHREADS, smem_bytes>>>(
        x, W_ih0, W_hh0, b_ih0, b_hh0,
        W_ih1, W_hh1, b_ih1, b_hh1,
        W_out, b_out, out);
}